// round 3
// baseline (speedup 1.0000x reference)
#include <cuda_runtime.h>
#include <math.h>

#define NN 256
#define NM 240
#define NB 120
#define ITERS 30
#define PER_LAUNCH (62 * NB)   // 62 grid barriers per launch, 120 arrivals each

// ---------------- device scratch ----------------
__device__ float4   g_At4[60 * NM];   // [kb*240+j] = A[j][16+4kb..16+4kb+3]
__device__ float4   g_Ab4[60 * NM];   // [jb*240+k] = A[4jb+r][16+k], r=0..3
__device__ float    g_Gmat[NM * NM];  // sigmoid(Gl) snapshot (pre-update)
__device__ float    g_tau[NN];
__device__ float    g_lodd[NM];
__device__ float    g_lord[NM];
__device__ int      g_stop;
__device__ unsigned g_barcnt;         // monotonic across graph replays

// ---------------- helpers ----------------
static __device__ __forceinline__ unsigned ld_acq(const unsigned* p) {
    unsigned v; asm volatile("ld.acquire.gpu.global.u32 %0,[%1];" : "=r"(v) : "l"(p)); return v;
}
static __device__ __forceinline__ float ldcg(const float* p) {
    float v; asm volatile("ld.global.cg.f32 %0,[%1];" : "=f"(v) : "l"(p)); return v;
}
static __device__ __forceinline__ int ldcg_i(const int* p) {
    int v; asm volatile("ld.global.cg.s32 %0,[%1];" : "=r"(v) : "l"(p)); return v;
}
static __device__ __forceinline__ float sigm(float x) { return 1.0f / (1.0f + __expf(-x)); }

// Deterministic block-wide sum over 256 threads; full sum valid on thread 0.
static __device__ __forceinline__ float bred(float v, float* red) {
    const unsigned m = 0xffffffffu;
    v += __shfl_down_sync(m, v, 16); v += __shfl_down_sync(m, v, 8);
    v += __shfl_down_sync(m, v, 4);  v += __shfl_down_sync(m, v, 2);
    v += __shfl_down_sync(m, v, 1);
    if ((threadIdx.x & 31) == 0) red[threadIdx.x >> 5] = v;
    __syncthreads();
    float r = (threadIdx.x < 8) ? red[threadIdx.x] : 0.0f;
    if (threadIdx.x < 32) {
        r += __shfl_down_sync(m, r, 4); r += __shfl_down_sync(m, r, 2);
        r += __shfl_down_sync(m, r, 1);
    }
    __syncthreads();
    return r;
}

// Grid barrier: monotonic counter; exactly 62 calls/launch keeps the
// counter a multiple of PER_LAUNCH at every launch boundary.
#define GRIDBAR() do { __syncthreads();                                   \
    if (tx == 0) { __threadfence(); atomicAdd(&g_barcnt, 1u);             \
        while (ld_acq(&g_barcnt) < bartgt) __nanosleep(64); }             \
    bartgt += NB; __syncthreads(); } while (0)

// ---------------- persistent kernel ----------------
__global__ void __launch_bounds__(256) gflow(
    const float* __restrict__ A, const float* __restrict__ Gl0,
    const float* __restrict__ tau0, float* __restrict__ out)
{
    const int b  = blockIdx.x;
    const int tx = threadIdx.x;
    const int r0 = b, r1 = b + NB;

    __shared__ float4 Gna[60], Gnb[60], Dsa[60], Dsb[60];
    __shared__ float  taus[NN];
    __shared__ float  red[8];

    unsigned bartgt = (ld_acq(&g_barcnt) / PER_LAUNCH) * PER_LAUNCH + NB;

    // ---- init: repack A (both layouts), load params into registers ----
    if (tx < 120) {
        int e = b * 120 + tx, kb = e / NM, j = e % NM;
        g_At4[e] = *(const float4*)(A + j * NN + 16 + 4 * kb);
        float4 v;
        v.x = A[(4 * kb + 0) * NN + 16 + j];
        v.y = A[(4 * kb + 1) * NN + 16 + j];
        v.z = A[(4 * kb + 2) * NN + 16 + j];
        v.w = A[(4 * kb + 3) * NN + 16 + j];
        g_Ab4[e] = v;
    }
    float gl0 = 0.f, gl1 = 0.f, mg0 = 0.f, vg0 = 0.f, mg1 = 0.f, vg1 = 0.f;
    if (tx < NM) { gl0 = Gl0[r0 * NM + tx]; gl1 = Gl0[r1 * NM + tx]; }
    if (tx == 0) {
        g_tau[r0] = tau0[r0]; g_tau[r1] = tau0[r1];
        if (b < 16) g_tau[240 + b] = tau0[240 + b];
        if (b == 0) g_stop = 0;
    }
    float mt1 = 0, vt1 = 0, mt2 = 0, vt2 = 0, mt3 = 0, vt3 = 0;  // tau Adam (thread 0)
    GRIDBAR();  // #1

    double b1t = 1.0, b2t = 1.0;
    float s0 = 0.f, s1 = 0.f;
    int stop = 0;

    for (int t = 0; t < ITERS; ++t) {
        b1t *= 0.9; b2t *= 0.999;
        const float bc1 = (float)(1.0 / (1.0 - b1t));
        const float bc2 = (float)(1.0 / (1.0 - b2t));
        if (!stop) stop = ldcg_i(&g_stop);

        // ---------- phase A: forward + losses + grad G + Adam(G) ----------
        if (!stop) {
            taus[tx] = ldcg(&g_tau[tx]);
            if (tx < NM) {
                s0 = sigm(gl0); s1 = sigm(gl1);
                ((float*)Gna)[tx] = -2.f * s0;
                ((float*)Gnb)[tx] = -2.f * s1;
                g_Gmat[r0 * NM + tx] = s0;
                g_Gmat[r1 * NM + tx] = s1;
            }
            __syncthreads();

            float la = 0.f, lb = 0.f, lo0 = 0.f, lo1 = 0.f;
            if (tx < NM) {
                const int j = tx;
                float4 pa = make_float4(1.f, 1.f, 1.f, 1.f);
                float4 pb = make_float4(1.f, 1.f, 1.f, 1.f);
                #pragma unroll 4
                for (int kb = 0; kb < 60; ++kb) {
                    float4 a = g_At4[kb * NM + j];
                    float4 ga = Gna[kb], gb = Gnb[kb];
                    pa.x *= fmaf(a.x, ga.x, 1.f); pa.y *= fmaf(a.y, ga.y, 1.f);
                    pa.z *= fmaf(a.z, ga.z, 1.f); pa.w *= fmaf(a.w, ga.w, 1.f);
                    pb.x *= fmaf(a.x, gb.x, 1.f); pb.y *= fmaf(a.y, gb.y, 1.f);
                    pb.z *= fmaf(a.z, gb.z, 1.f); pb.w *= fmaf(a.w, gb.w, 1.f);
                }
                float Pa = (pa.x * pa.y) * (pa.z * pa.w);
                float Pb = (pb.x * pb.y) * (pb.z * pb.w);
                float ea = Pa - ((j == r0) ? -1.f : 1.f);
                float eb = Pb - ((j == r1) ? -1.f : 1.f);
                la = ea * ea; lb = eb * eb;
                ((float*)Dsa)[j] = ea * Pa * (1.f / 480.f);
                ((float*)Dsb)[j] = eb * Pb * (1.f / 480.f);
                float d0 = fmaxf(taus[r0] - taus[16 + j] + 0.1f, 0.f);
                float d1 = fmaxf(taus[r1] - taus[16 + j] + 0.1f, 0.f);
                lo0 = s0 * d0 * d0; lo1 = s1 * d1 * d1;
            }
            __syncthreads();
            float SA = bred(la, red), SB = bred(lb, red);
            float L0 = bred(lo0, red), L1 = bred(lo1, red);
            if (tx == 0) {
                g_lodd[r0] = SA; g_lodd[r1] = SB;
                g_lord[r0] = L0; g_lord[r1] = L1;
            }

            if (tx < NM) {   // backward, thread = k (even/odd grouping as R1)
                const int k = tx;
                const float gna = -2.f * s0, gnb = -2.f * s1;
                float e0 = 0.f, o0 = 0.f, e1 = 0.f, o1 = 0.f;
                #pragma unroll 4
                for (int jb = 0; jb < 60; ++jb) {
                    float4 a = g_Ab4[jb * NM + k];
                    float4 dA = Dsa[jb], dB = Dsb[jb];
                    float t0, t1, t2, t3, q;
                    t0 = fmaf(a.x, gna, 1.f); t1 = fmaf(a.y, gna, 1.f);
                    t2 = fmaf(a.z, gna, 1.f); t3 = fmaf(a.w, gna, 1.f);
                    q = __fdividef(dA.x * a.x, t0); e0 += (t0 != 0.f) ? q : 0.f;
                    q = __fdividef(dA.y * a.y, t1); o0 += (t1 != 0.f) ? q : 0.f;
                    q = __fdividef(dA.z * a.z, t2); e0 += (t2 != 0.f) ? q : 0.f;
                    q = __fdividef(dA.w * a.w, t3); o0 += (t3 != 0.f) ? q : 0.f;
                    t0 = fmaf(a.x, gnb, 1.f); t1 = fmaf(a.y, gnb, 1.f);
                    t2 = fmaf(a.z, gnb, 1.f); t3 = fmaf(a.w, gnb, 1.f);
                    q = __fdividef(dB.x * a.x, t0); e1 += (t0 != 0.f) ? q : 0.f;
                    q = __fdividef(dB.y * a.y, t1); o1 += (t1 != 0.f) ? q : 0.f;
                    q = __fdividef(dB.z * a.z, t2); e1 += (t2 != 0.f) ? q : 0.f;
                    q = __fdividef(dB.w * a.w, t3); o1 += (t3 != 0.f) ? q : 0.f;
                }
                float d0 = fmaxf(taus[r0] - taus[16 + k] + 0.1f, 0.f);
                float d1 = fmaxf(taus[r1] - taus[16 + k] + 0.1f, 0.f);
                float gr0 = (-2.f * (e0 + o0) + d0 * d0 * (1.f / 61440.f)) * (s0 * (1.f - s0));
                float gr1 = (-2.f * (e1 + o1) + d1 * d1 * (1.f / 61440.f)) * (s1 * (1.f - s1));
                mg0 = 0.9f * mg0 + 0.1f * gr0; vg0 = 0.999f * vg0 + 0.001f * gr0 * gr0;
                mg1 = 0.9f * mg1 + 0.1f * gr1; vg1 = 0.999f * vg1 + 0.001f * gr1 * gr1;
                gl0 -= 0.1f * (mg0 * bc1) / (sqrtf(vg0 * bc2) + 1e-8f);
                gl1 -= 0.1f * (mg1 * bc1) / (sqrtf(vg1 * bc2) + 1e-8f);
            }
        }
        GRIDBAR();  // per-iter bar 1

        // ---------- phase B: tau grads + Adam(tau) + stop ----------
        if (!stop) {
            float S1a = 0.f, S2a = 0.f, S1b = 0.f, S2b = 0.f, S2c = 0.f;
            if (tx < NM) {
                float rA = fmaxf(taus[r0] - taus[16 + tx] + 0.1f, 0.f);
                float rB = fmaxf(taus[r1] - taus[16 + tx] + 0.1f, 0.f);
                S1a = s0 * rA; S1b = s1 * rB;
                float ti = taus[tx];
                if (r0 >= 16)
                    S2a = ldcg(&g_Gmat[tx * NM + r0 - 16]) * fmaxf(ti - taus[r0] + 0.1f, 0.f);
                S2b = ldcg(&g_Gmat[tx * NM + r1 - 16]) * fmaxf(ti - taus[r1] + 0.1f, 0.f);
                if (b < 16)
                    S2c = ldcg(&g_Gmat[tx * NM + 224 + b]) * fmaxf(ti - taus[240 + b] + 0.1f, 0.f);
            }
            S1a = bred(S1a, red); S2a = bred(S2a, red);
            S1b = bred(S1b, red); S2b = bred(S2b, red);
            if (b < 16) S2c = bred(S2c, red);

            float lsum = 0.f;
            if (b == 0) {   // loss combine for stop check
                float v = (tx < NM) ? ldcg(&g_lodd[tx]) * (1.f / 960.f)
                                    + ldcg(&g_lord[tx]) * (1.f / 61440.f) : 0.f;
                lsum = bred(v, red);
            }

            if (tx == 0) {
                float g1 = (2.f / 61440.f) * (S1a - S2a);
                mt1 = 0.9f * mt1 + 0.1f * g1; vt1 = 0.999f * vt1 + 0.001f * g1 * g1;
                g_tau[r0] = taus[r0] - 0.1f * (mt1 * bc1) / (sqrtf(vt1 * bc2) + 1e-8f);
                float g2 = (2.f / 61440.f) * (S1b - S2b);
                mt2 = 0.9f * mt2 + 0.1f * g2; vt2 = 0.999f * vt2 + 0.001f * g2 * g2;
                g_tau[r1] = taus[r1] - 0.1f * (mt2 * bc1) / (sqrtf(vt2 * bc2) + 1e-8f);
                if (b < 16) {
                    float g3 = (2.f / 61440.f) * (0.f - S2c);
                    mt3 = 0.9f * mt3 + 0.1f * g3; vt3 = 0.999f * vt3 + 0.001f * g3 * g3;
                    g_tau[240 + b] = taus[240 + b] - 0.1f * (mt3 * bc1) / (sqrtf(vt3 * bc2) + 1e-8f);
                }
                if (b == 0 && lsum < 1e-3f) g_stop = 1;
            }
        }
        GRIDBAR();  // per-iter bar 2
    }

    // ---------- epilogue: final loss at p_final ----------
    if (tx < NM) {
        s0 = sigm(gl0); s1 = sigm(gl1);
        ((float*)Gna)[tx] = -2.f * s0;
        ((float*)Gnb)[tx] = -2.f * s1;
    }
    taus[tx] = ldcg(&g_tau[tx]);
    __syncthreads();
    {
        float la = 0.f, lb = 0.f, lo0 = 0.f, lo1 = 0.f;
        if (tx < NM) {
            const int j = tx;
            float4 pa = make_float4(1.f, 1.f, 1.f, 1.f);
            float4 pb = make_float4(1.f, 1.f, 1.f, 1.f);
            #pragma unroll 4
            for (int kb = 0; kb < 60; ++kb) {
                float4 a = g_At4[kb * NM + j];
                float4 ga = Gna[kb], gb = Gnb[kb];
                pa.x *= fmaf(a.x, ga.x, 1.f); pa.y *= fmaf(a.y, ga.y, 1.f);
                pa.z *= fmaf(a.z, ga.z, 1.f); pa.w *= fmaf(a.w, ga.w, 1.f);
                pb.x *= fmaf(a.x, gb.x, 1.f); pb.y *= fmaf(a.y, gb.y, 1.f);
                pb.z *= fmaf(a.z, gb.z, 1.f); pb.w *= fmaf(a.w, gb.w, 1.f);
            }
            float Pa = (pa.x * pa.y) * (pa.z * pa.w);
            float Pb = (pb.x * pb.y) * (pb.z * pb.w);
            float ea = Pa - ((j == r0) ? -1.f : 1.f);
            float eb = Pb - ((j == r1) ? -1.f : 1.f);
            la = ea * ea; lb = eb * eb;
            float d0 = fmaxf(taus[r0] - taus[16 + j] + 0.1f, 0.f);
            float d1 = fmaxf(taus[r1] - taus[16 + j] + 0.1f, 0.f);
            lo0 = s0 * d0 * d0; lo1 = s1 * d1 * d1;
        }
        float SA = bred(la, red), SB = bred(lb, red);
        float L0 = bred(lo0, red), L1 = bred(lo1, red);
        if (tx == 0) {
            g_lodd[r0] = SA; g_lodd[r1] = SB;
            g_lord[r0] = L0; g_lord[r1] = L1;
        }
    }
    GRIDBAR();  // #62
    if (b == 0) {
        float v = (tx < NM) ? ldcg(&g_lodd[tx]) * (1.f / 960.f)
                            + ldcg(&g_lord[tx]) * (1.f / 61440.f) : 0.f;
        float L = bred(v, red);
        if (tx == 0) out[0] = L;
    }
}

// ---------------- launch ----------------
extern "C" void kernel_launch(void* const* d_in, const int* in_sizes, int n_in,
                              void* d_out, int out_size) {
    const float* A    = (const float*)d_in[0];
    const float* Gl0  = (const float*)d_in[1];
    const float* tau0 = (const float*)d_in[2];
    gflow<<<NB, 256>>>(A, Gl0, tau0, (float*)d_out);
}

// round 4
// speedup vs baseline: 1.4704x; 1.4704x over previous
#include <cuda_runtime.h>
#include <math.h>

#define NN 256
#define NM 240
#define NB 120
#define ITERS 30
#define PER_LAUNCH (62 * NB)   // 62 grid barriers per launch, 120 arrivals each

// ---------------- device scratch ----------------
__device__ float4   g_At4[60 * NM];   // [kb*240+j] = A[j][16+4kb..16+4kb+3]
__device__ float4   g_Ab4[60 * NM];   // [jb*240+k] = A[4jb+r][16+k]
__device__ float    g_Gmat[NM * NM];  // sigmoid(Gl) snapshot (pre-update)
__device__ float    g_tau[NN];
__device__ float    g_lodd[NM];
__device__ float    g_lord[NM];
__device__ int      g_stop;
__device__ unsigned g_barcnt;         // monotonic across graph replays

// ---------------- helpers ----------------
static __device__ __forceinline__ unsigned ld_acq(const unsigned* p) {
    unsigned v; asm volatile("ld.acquire.gpu.global.u32 %0,[%1];" : "=r"(v) : "l"(p)); return v;
}
static __device__ __forceinline__ float ldcg(const float* p) {
    float v; asm volatile("ld.global.cg.f32 %0,[%1];" : "=f"(v) : "l"(p)); return v;
}
static __device__ __forceinline__ int ldcg_i(const int* p) {
    int v; asm volatile("ld.global.cg.s32 %0,[%1];" : "=r"(v) : "l"(p)); return v;
}
static __device__ __forceinline__ float rcpa(float x) {
    float r; asm("rcp.approx.f32 %0,%1;" : "=f"(r) : "f"(x)); return r;
}
static __device__ __forceinline__ float sigm(float x) { return 1.0f / (1.0f + __expf(-x)); }

// Deterministic block-wide sum over 1024 threads; full sum valid on thread 0.
static __device__ __forceinline__ float bred(float v, volatile float* red) {
    const unsigned m = 0xffffffffu;
    v += __shfl_down_sync(m, v, 16); v += __shfl_down_sync(m, v, 8);
    v += __shfl_down_sync(m, v, 4);  v += __shfl_down_sync(m, v, 2);
    v += __shfl_down_sync(m, v, 1);
    if ((threadIdx.x & 31) == 0) red[threadIdx.x >> 5] = v;
    __syncthreads();
    float r = (threadIdx.x < 32) ? red[threadIdx.x] : 0.f;
    if (threadIdx.x < 32) {
        r += __shfl_down_sync(m, r, 16); r += __shfl_down_sync(m, r, 8);
        r += __shfl_down_sync(m, r, 4);  r += __shfl_down_sync(m, r, 2);
        r += __shfl_down_sync(m, r, 1);
    }
    __syncthreads();
    return r;
}

#define GRIDBAR() do { __syncthreads(); __threadfence();                  \
    if (tx == 0) { atomicAdd(&g_barcnt, 1u);                              \
        while (ld_acq(&g_barcnt) < bartgt) __nanosleep(64); }             \
    bartgt += NB; __syncthreads(); } while (0)

// paired reciprocal accumulate: acc += n0/t0 + n1/t1  (exact-zero fallback)
#define PAIRQ(n0, n1, t0, t1, acc) do {                                   \
    float _pr = (t0) * (t1);                                              \
    if (_pr != 0.f) acc += ((n0) * (t1) + (n1) * (t0)) * rcpa(_pr);       \
    else acc += ((t0) != 0.f ? __fdividef((n0), (t0)) : 0.f)              \
              + ((t1) != 0.f ? __fdividef((n1), (t1)) : 0.f);             \
} while (0)

// ---------------- persistent kernel ----------------
__global__ void __launch_bounds__(1024, 1) gflow(
    const float* __restrict__ A, const float* __restrict__ Gl0,
    const float* __restrict__ tau0, float* __restrict__ out)
{
    const int b  = blockIdx.x;
    const int tx = threadIdx.x;
    const int Q  = tx >> 8;      // quarter 0..3
    const int U  = tx & 255;     // lane within quarter
    const int r0 = b, r1 = b + NB;

    __shared__ float4 Gna4[60], Gnb4[60];   // -2*sigmoid rows r0/r1
    __shared__ float4 DsA4[60], DsB4[60];   // (P-T)*P/480
    __shared__ float  pfA[4 * NM], pfB[4 * NM];  // quarter partials
    __shared__ float  taus[NN];
    __shared__ float  red[32];
    float* GnaF = (float*)Gna4;
    float* GnbF = (float*)Gnb4;

    unsigned bartgt = (ld_acq(&g_barcnt) / PER_LAUNCH) * PER_LAUNCH + NB;

    // ---- init: repack A, load params into registers ----
    if (tx < 120) {
        int e = b * 120 + tx, kb = e / NM, j = e % NM;
        g_At4[e] = *(const float4*)(A + j * NN + 16 + 4 * kb);
        float4 v;
        v.x = A[(4 * kb + 0) * NN + 16 + j];
        v.y = A[(4 * kb + 1) * NN + 16 + j];
        v.z = A[(4 * kb + 2) * NN + 16 + j];
        v.w = A[(4 * kb + 3) * NN + 16 + j];
        g_Ab4[e] = v;
    }
    float gl = 0.f, mg = 0.f, vg = 0.f;     // Adam state for (row = Q?r1:r0, k = U)
    if (Q < 2 && U < NM) gl = Gl0[(Q ? r1 : r0) * NM + U];
    if (tx == 0) {
        g_tau[r0] = tau0[r0]; g_tau[r1] = tau0[r1];
        if (b < 16) g_tau[240 + b] = tau0[240 + b];
        if (b == 0) g_stop = 0;
    }
    float mt1 = 0, vt1 = 0, mt2 = 0, vt2 = 0, mt3 = 0, vt3 = 0;  // tau Adam (tx 0)
    GRIDBAR();  // #1

    double b1t = 1.0, b2t = 1.0;
    int stop = 0;

    for (int t = 0; t < ITERS; ++t) {
        b1t *= 0.9; b2t *= 0.999;
        const float bc1 = (float)(1.0 / (1.0 - b1t));
        const float bc2 = (float)(1.0 / (1.0 - b2t));
        if (!stop) stop = ldcg_i(&g_stop);

        // ---------- phase A: forward + losses + grad G + Adam(G) ----------
        if (!stop) {
            if (tx < NN) taus[tx] = ldcg(&g_tau[tx]);
            if (Q < 2 && U < NM) {
                float s = sigm(gl);
                (Q ? GnbF : GnaF)[U] = -2.f * s;
                g_Gmat[(Q ? r1 : r0) * NM + U] = s;
            }
            __syncthreads();

            // forward: thread (Q, j=U) -> partial product over k-quarter Q
            if (U < NM) {
                const int j = U;
                float4 pa = make_float4(1.f, 1.f, 1.f, 1.f);
                float4 pb = make_float4(1.f, 1.f, 1.f, 1.f);
                #pragma unroll 5
                for (int c = 0; c < 15; ++c) {
                    int kb = 15 * Q + c;
                    float4 a = g_At4[kb * NM + j];
                    float4 ga = Gna4[kb], gb = Gnb4[kb];
                    pa.x *= fmaf(a.x, ga.x, 1.f); pa.y *= fmaf(a.y, ga.y, 1.f);
                    pa.z *= fmaf(a.z, ga.z, 1.f); pa.w *= fmaf(a.w, ga.w, 1.f);
                    pb.x *= fmaf(a.x, gb.x, 1.f); pb.y *= fmaf(a.y, gb.y, 1.f);
                    pb.z *= fmaf(a.z, gb.z, 1.f); pb.w *= fmaf(a.w, gb.w, 1.f);
                }
                pfA[Q * NM + j] = (pa.x * pa.y) * (pa.z * pa.w);
                pfB[Q * NM + j] = (pb.x * pb.y) * (pb.z * pb.w);
            }
            __syncthreads();

            float la = 0.f, lb = 0.f, lo0 = 0.f, lo1 = 0.f;
            if (Q == 0 && U < NM) {
                const int j = U;
                float Pa = (pfA[j] * pfA[NM + j]) * (pfA[2 * NM + j] * pfA[3 * NM + j]);
                float Pb = (pfB[j] * pfB[NM + j]) * (pfB[2 * NM + j] * pfB[3 * NM + j]);
                float ea = Pa - ((j == r0) ? -1.f : 1.f);
                float eb = Pb - ((j == r1) ? -1.f : 1.f);
                la = ea * ea; lb = eb * eb;
                ((float*)DsA4)[j] = ea * Pa * (1.f / 480.f);
                ((float*)DsB4)[j] = eb * Pb * (1.f / 480.f);
                float s0j = -0.5f * GnaF[j], s1j = -0.5f * GnbF[j];
                float d0 = fmaxf(taus[r0] - taus[16 + j] + 0.1f, 0.f);
                float d1 = fmaxf(taus[r1] - taus[16 + j] + 0.1f, 0.f);
                lo0 = s0j * d0 * d0; lo1 = s1j * d1 * d1;
            }
            float SA = bred(la, red), SB = bred(lb, red);
            float L0 = bred(lo0, red), L1 = bred(lo1, red);
            if (tx == 0) {
                g_lodd[r0] = SA; g_lodd[r1] = SB;
                g_lord[r0] = L0; g_lord[r1] = L1;
            }
            // (bred syncthreads also made Ds visible)

            // backward: thread (Q, k=U) -> partial sum over j-quarter Q
            if (U < NM) {
                const int k = U;
                const float gna = GnaF[k], gnb = GnbF[k];
                float sA0 = 0.f, sA1 = 0.f, sB0 = 0.f, sB1 = 0.f;
                #pragma unroll 5
                for (int c = 0; c < 15; ++c) {
                    int jb = 15 * Q + c;
                    float4 a = g_Ab4[jb * NM + k];
                    float4 dA = DsA4[jb], dB = DsB4[jb];
                    float t0 = fmaf(a.x, gna, 1.f), t1 = fmaf(a.y, gna, 1.f);
                    float t2 = fmaf(a.z, gna, 1.f), t3 = fmaf(a.w, gna, 1.f);
                    PAIRQ(dA.x * a.x, dA.y * a.y, t0, t1, sA0);
                    PAIRQ(dA.z * a.z, dA.w * a.w, t2, t3, sA1);
                    t0 = fmaf(a.x, gnb, 1.f); t1 = fmaf(a.y, gnb, 1.f);
                    t2 = fmaf(a.z, gnb, 1.f); t3 = fmaf(a.w, gnb, 1.f);
                    PAIRQ(dB.x * a.x, dB.y * a.y, t0, t1, sB0);
                    PAIRQ(dB.z * a.z, dB.w * a.w, t2, t3, sB1);
                }
                pfA[Q * NM + k] = sA0 + sA1;
                pfB[Q * NM + k] = sB0 + sB1;
            }
            __syncthreads();

            if (Q < 2 && U < NM) {
                const int k = U;
                const float* pf = Q ? pfB : pfA;
                float S = (pf[k] + pf[NM + k]) + (pf[2 * NM + k] + pf[3 * NM + k]);
                float s = -0.5f * (Q ? GnbF : GnaF)[k];
                float d = fmaxf(taus[Q ? r1 : r0] - taus[16 + k] + 0.1f, 0.f);
                float grad = (-2.f * S + d * d * (1.f / 61440.f)) * (s * (1.f - s));
                mg = 0.9f * mg + 0.1f * grad;
                vg = 0.999f * vg + 0.001f * grad * grad;
                gl -= 0.1f * (mg * bc1) / (sqrtf(vg * bc2) + 1e-8f);
            }
        }
        GRIDBAR();  // per-iter bar 1

        // ---------- phase B: tau grads + Adam(tau) + stop ----------
        if (!stop) {
            float S1a = 0.f, S2a = 0.f, S1b = 0.f, S2b = 0.f, S2c = 0.f, v = 0.f;
            if (Q == 0 && U < NM) {
                float s0 = -0.5f * GnaF[U], s1 = -0.5f * GnbF[U];
                S1a = s0 * fmaxf(taus[r0] - taus[16 + U] + 0.1f, 0.f);
                S1b = s1 * fmaxf(taus[r1] - taus[16 + U] + 0.1f, 0.f);
                float ti = taus[U];
                if (r0 >= 16)
                    S2a = ldcg(&g_Gmat[U * NM + r0 - 16]) * fmaxf(ti - taus[r0] + 0.1f, 0.f);
                S2b = ldcg(&g_Gmat[U * NM + r1 - 16]) * fmaxf(ti - taus[r1] + 0.1f, 0.f);
                if (b < 16)
                    S2c = ldcg(&g_Gmat[U * NM + 224 + b]) * fmaxf(ti - taus[240 + b] + 0.1f, 0.f);
                v = ldcg(&g_lodd[U]) * (1.f / 960.f) + ldcg(&g_lord[U]) * (1.f / 61440.f);
            }
            S1a = bred(S1a, red); S2a = bred(S2a, red);
            S1b = bred(S1b, red); S2b = bred(S2b, red);
            S2c = bred(S2c, red);
            float lsum = bred(v, red);

            if (tx == 0) {
                float g1 = (2.f / 61440.f) * (S1a - S2a);
                mt1 = 0.9f * mt1 + 0.1f * g1; vt1 = 0.999f * vt1 + 0.001f * g1 * g1;
                g_tau[r0] = taus[r0] - 0.1f * (mt1 * bc1) / (sqrtf(vt1 * bc2) + 1e-8f);
                float g2 = (2.f / 61440.f) * (S1b - S2b);
                mt2 = 0.9f * mt2 + 0.1f * g2; vt2 = 0.999f * vt2 + 0.001f * g2 * g2;
                g_tau[r1] = taus[r1] - 0.1f * (mt2 * bc1) / (sqrtf(vt2 * bc2) + 1e-8f);
                if (b < 16) {
                    float g3 = (2.f / 61440.f) * (0.f - S2c);
                    mt3 = 0.9f * mt3 + 0.1f * g3; vt3 = 0.999f * vt3 + 0.001f * g3 * g3;
                    g_tau[240 + b] = taus[240 + b] - 0.1f * (mt3 * bc1) / (sqrtf(vt3 * bc2) + 1e-8f);
                }
                if (b == 0 && lsum < 1e-3f) g_stop = 1;
            }
        }
        GRIDBAR();  // per-iter bar 2
    }

    // ---------- epilogue: final loss at p_final ----------
    if (tx < NN) taus[tx] = ldcg(&g_tau[tx]);
    if (Q < 2 && U < NM) (Q ? GnbF : GnaF)[U] = -2.f * sigm(gl);
    __syncthreads();
    if (U < NM) {
        const int j = U;
        float4 pa = make_float4(1.f, 1.f, 1.f, 1.f);
        float4 pb = make_float4(1.f, 1.f, 1.f, 1.f);
        #pragma unroll 5
        for (int c = 0; c < 15; ++c) {
            int kb = 15 * Q + c;
            float4 a = g_At4[kb * NM + j];
            float4 ga = Gna4[kb], gb = Gnb4[kb];
            pa.x *= fmaf(a.x, ga.x, 1.f); pa.y *= fmaf(a.y, ga.y, 1.f);
            pa.z *= fmaf(a.z, ga.z, 1.f); pa.w *= fmaf(a.w, ga.w, 1.f);
            pb.x *= fmaf(a.x, gb.x, 1.f); pb.y *= fmaf(a.y, gb.y, 1.f);
            pb.z *= fmaf(a.z, gb.z, 1.f); pb.w *= fmaf(a.w, gb.w, 1.f);
        }
        pfA[Q * NM + j] = (pa.x * pa.y) * (pa.z * pa.w);
        pfB[Q * NM + j] = (pb.x * pb.y) * (pb.z * pb.w);
    }
    __syncthreads();
    {
        float la = 0.f, lb = 0.f, lo0 = 0.f, lo1 = 0.f;
        if (Q == 0 && U < NM) {
            const int j = U;
            float Pa = (pfA[j] * pfA[NM + j]) * (pfA[2 * NM + j] * pfA[3 * NM + j]);
            float Pb = (pfB[j] * pfB[NM + j]) * (pfB[2 * NM + j] * pfB[3 * NM + j]);
            float ea = Pa - ((j == r0) ? -1.f : 1.f);
            float eb = Pb - ((j == r1) ? -1.f : 1.f);
            la = ea * ea; lb = eb * eb;
            float s0j = -0.5f * GnaF[j], s1j = -0.5f * GnbF[j];
            float d0 = fmaxf(taus[r0] - taus[16 + j] + 0.1f, 0.f);
            float d1 = fmaxf(taus[r1] - taus[16 + j] + 0.1f, 0.f);
            lo0 = s0j * d0 * d0; lo1 = s1j * d1 * d1;
        }
        float SA = bred(la, red), SB = bred(lb, red);
        float L0 = bred(lo0, red), L1 = bred(lo1, red);
        if (tx == 0) {
            g_lodd[r0] = SA; g_lodd[r1] = SB;
            g_lord[r0] = L0; g_lord[r1] = L1;
        }
    }
    GRIDBAR();  // #62
    if (b == 0) {
        float v = (Q == 0 && U < NM)
            ? ldcg(&g_lodd[U]) * (1.f / 960.f) + ldcg(&g_lord[U]) * (1.f / 61440.f) : 0.f;
        float L = bred(v, red);
        if (tx == 0) out[0] = L;
    }
}

// ---------------- launch ----------------
extern "C" void kernel_launch(void* const* d_in, const int* in_sizes, int n_in,
                              void* d_out, int out_size) {
    const float* A    = (const float*)d_in[0];
    const float* Gl0  = (const float*)d_in[1];
    const float* tau0 = (const float*)d_in[2];
    gflow<<<NB, 1024>>>(A, Gl0, tau0, (float*)d_out);
}

// round 5
// speedup vs baseline: 1.7696x; 1.2034x over previous
#include <cuda_runtime.h>
#include <math.h>

#define NN 256
#define NM 240
#define NB 120
#define ITERS 30
#define PER_LAUNCH (62 * NB)   // 62 grid barriers per launch, 120 arrivals each

typedef unsigned long long u64;
union F2 { u64 u; float2 f; };
#define ONES2 0x3f8000003f800000ULL

// ---------------- device scratch ----------------
__device__ float4   g_At4[60 * NM];   // [kb*240+j] = A[j][16+4kb..16+4kb+3]
__device__ float4   g_Ab4[60 * NM];   // [jb*240+k] = A[4jb+r][16+k]
__device__ float    g_Gmat[NM * NM];  // sigmoid(Gl) snapshot (pre-update)
__device__ float    g_tau[NN];
__device__ float    g_lodd[NM];
__device__ float    g_lord[NM];
__device__ int      g_stop;
__device__ unsigned g_barcnt;         // monotonic across graph replays

// ---------------- helpers ----------------
static __device__ __forceinline__ unsigned ld_acq(const unsigned* p) {
    unsigned v; asm volatile("ld.acquire.gpu.global.u32 %0,[%1];" : "=r"(v) : "l"(p)); return v;
}
static __device__ __forceinline__ float ldcg(const float* p) {
    float v; asm volatile("ld.global.cg.f32 %0,[%1];" : "=f"(v) : "l"(p)); return v;
}
static __device__ __forceinline__ int ldcg_i(const int* p) {
    int v; asm volatile("ld.global.cg.s32 %0,[%1];" : "=r"(v) : "l"(p)); return v;
}
static __device__ __forceinline__ float rcpa(float x) {
    float r; asm("rcp.approx.f32 %0,%1;" : "=f"(r) : "f"(x)); return r;
}
static __device__ __forceinline__ u64 fma2_(u64 a, u64 b, u64 c) {
    u64 d; asm("fma.rn.f32x2 %0,%1,%2,%3;" : "=l"(d) : "l"(a), "l"(b), "l"(c)); return d;
}
static __device__ __forceinline__ u64 mul2_(u64 a, u64 b) {
    u64 d; asm("mul.rn.f32x2 %0,%1,%2;" : "=l"(d) : "l"(a), "l"(b)); return d;
}
static __device__ __forceinline__ float sigm(float x) { return 1.0f / (1.0f + __expf(-x)); }

// Quarter-segmented reduction: each 256-lane quarter sums its own value.
// Result for quarter q lands in resQ[q + off]. 2 block barriers total.
#define QRED4(val, off) do {                                              \
    float _v = (val);                                                     \
    _v += __shfl_down_sync(0xffffffffu, _v, 16);                          \
    _v += __shfl_down_sync(0xffffffffu, _v, 8);                           \
    _v += __shfl_down_sync(0xffffffffu, _v, 4);                           \
    _v += __shfl_down_sync(0xffffffffu, _v, 2);                           \
    _v += __shfl_down_sync(0xffffffffu, _v, 1);                           \
    if ((tx & 31) == 0) wsum[tx >> 5] = _v;                               \
    __syncthreads();                                                      \
    if (U == 0) { float _s = 0.f;                                         \
        for (int _w = 0; _w < 8; ++_w) _s += wsum[Q * 8 + _w];            \
        resQ[Q + (off)] = _s; }                                           \
    __syncthreads(); } while (0)

#define GRIDBAR() do { __syncthreads();                                   \
    if (tx == 0) { __threadfence(); atomicAdd(&g_barcnt, 1u);             \
        while (ld_acq(&g_barcnt) < bartgt) { } }                          \
    bartgt += NB; __syncthreads(); } while (0)

// quad leave-one-out accumulate: acc += sum_i n_i / t_i  (t,n packed pairs)
#define QUADACC(t01u, t23u, n01u, n23u, acc) do {                         \
    F2 _t0; _t0.u = (t01u); F2 _t1; _t1.u = (t23u);                       \
    F2 _n0; _n0.u = (n01u); F2 _n1; _n1.u = (n23u);                       \
    float _P01 = _t0.f.x * _t0.f.y;                                       \
    float _P23 = _t1.f.x * _t1.f.y;                                       \
    float _T = _P01 * _P23;                                               \
    if (_T != 0.f) {                                                      \
        float _r = rcpa(_T);                                              \
        float _m1 = fmaf(_n0.f.y, _t0.f.x, _n0.f.x * _t0.f.y);            \
        float _m3 = fmaf(_n1.f.y, _t1.f.x, _n1.f.x * _t1.f.y);            \
        float _s = fmaf(_m3, _P01, _m1 * _P23);                           \
        acc = fmaf(_s, _r, acc);                                          \
    } else {                                                              \
        acc += (_t0.f.x != 0.f ? __fdividef(_n0.f.x, _t0.f.x) : 0.f)      \
             + (_t0.f.y != 0.f ? __fdividef(_n0.f.y, _t0.f.y) : 0.f)      \
             + (_t1.f.x != 0.f ? __fdividef(_n1.f.x, _t1.f.x) : 0.f)      \
             + (_t1.f.y != 0.f ? __fdividef(_n1.f.y, _t1.f.y) : 0.f);     \
    } } while (0)

// ---------------- persistent kernel ----------------
__global__ void __launch_bounds__(1024, 1) gflow(
    const float* __restrict__ A, const float* __restrict__ Gl0,
    const float* __restrict__ tau0, float* __restrict__ out)
{
    const int b  = blockIdx.x;
    const int tx = threadIdx.x;
    const int Q  = tx >> 8;      // quarter 0..3
    const int U  = tx & 255;     // lane within quarter
    const int r0 = b, r1 = b + NB;

    __shared__ u64   GnaP[120], GnbP[120];      // -2*sigmoid rows r0/r1 (packed)
    __shared__ float4 DsA4[60], DsB4[60];       // (P-T)*P/480
    __shared__ float pfA[4 * NM], pfB[4 * NM];  // quarter partials
    __shared__ float taus[NN];
    __shared__ float wsum[32];
    __shared__ float resQ[8];
    float* GnaF = (float*)GnaP;
    float* GnbF = (float*)GnbP;
    const ulonglong2* At8  = (const ulonglong2*)g_At4;
    const ulonglong2* Ab8  = (const ulonglong2*)g_Ab4;
    const ulonglong2* DsA8 = (const ulonglong2*)DsA4;
    const ulonglong2* DsB8 = (const ulonglong2*)DsB4;
    const ulonglong2* GnaP2 = (const ulonglong2*)GnaP;
    const ulonglong2* GnbP2 = (const ulonglong2*)GnbP;

    unsigned bartgt = (ld_acq(&g_barcnt) / PER_LAUNCH) * PER_LAUNCH + NB;

    // ---- init: repack A, load params into registers ----
    if (tx < 120) {
        int e = b * 120 + tx, kb = e / NM, j = e % NM;
        g_At4[e] = *(const float4*)(A + j * NN + 16 + 4 * kb);
        float4 v;
        v.x = A[(4 * kb + 0) * NN + 16 + j];
        v.y = A[(4 * kb + 1) * NN + 16 + j];
        v.z = A[(4 * kb + 2) * NN + 16 + j];
        v.w = A[(4 * kb + 3) * NN + 16 + j];
        g_Ab4[e] = v;
    }
    float gl = 0.f, mg = 0.f, vg = 0.f;     // Adam state (row = Q?r1:r0, k = U)
    if (Q < 2 && U < NM) gl = Gl0[(Q ? r1 : r0) * NM + U];
    if (tx == 0) {
        g_tau[r0] = tau0[r0]; g_tau[r1] = tau0[r1];
        if (b < 16) g_tau[240 + b] = tau0[240 + b];
        if (b == 0) g_stop = 0;
    }
    float mt1 = 0, vt1 = 0, mt2 = 0, vt2 = 0, mt3 = 0, vt3 = 0;  // tau Adam (tx 0)
    GRIDBAR();  // #1

    double b1t = 1.0, b2t = 1.0;
    int stop = 0;

    for (int t = 0; t < ITERS; ++t) {
        b1t *= 0.9; b2t *= 0.999;
        const float bc1 = (float)(1.0 / (1.0 - b1t));
        const float bc2 = (float)(1.0 / (1.0 - b2t));
        if (!stop) stop = ldcg_i(&g_stop);

        // ---------- phase A ----------
        if (!stop) {
            if (tx < NN) taus[tx] = ldcg(&g_tau[tx]);
            if (Q < 2 && U < NM) {
                float s = sigm(gl);
                (Q ? GnbF : GnaF)[U] = -2.f * s;
                g_Gmat[(Q ? r1 : r0) * NM + U] = s;
            }
            __syncthreads();

            // forward: thread (Q, j=U) -> product over k-quarter Q (packed)
            if (U < NM) {
                const int j = U;
                u64 pa0 = ONES2, pa1 = ONES2, pb0 = ONES2, pb1 = ONES2;
                #pragma unroll 5
                for (int c = 0; c < 15; ++c) {
                    int kb = 15 * Q + c;
                    ulonglong2 a  = At8[kb * NM + j];
                    ulonglong2 ga = GnaP2[kb];
                    ulonglong2 gb = GnbP2[kb];
                    pa0 = mul2_(pa0, fma2_(a.x, ga.x, ONES2));
                    pa1 = mul2_(pa1, fma2_(a.y, ga.y, ONES2));
                    pb0 = mul2_(pb0, fma2_(a.x, gb.x, ONES2));
                    pb1 = mul2_(pb1, fma2_(a.y, gb.y, ONES2));
                }
                F2 x0; x0.u = pa0; F2 x1; x1.u = pa1;
                pfA[Q * NM + j] = (x0.f.x * x0.f.y) * (x1.f.x * x1.f.y);
                x0.u = pb0; x1.u = pb1;
                pfB[Q * NM + j] = (x0.f.x * x0.f.y) * (x1.f.x * x1.f.y);
            }
            __syncthreads();

            // per-quarter epilogue: Q0 la+DsA, Q1 lb+DsB, Q2 lo0, Q3 lo1
            float v = 0.f;
            if (U < NM) {
                const int j = U;
                if (Q == 0) {
                    float P = (pfA[j] * pfA[NM + j]) * (pfA[2 * NM + j] * pfA[3 * NM + j]);
                    float e = P - ((j == r0) ? -1.f : 1.f);
                    v = e * e;
                    ((float*)DsA4)[j] = e * P * (1.f / 480.f);
                } else if (Q == 1) {
                    float P = (pfB[j] * pfB[NM + j]) * (pfB[2 * NM + j] * pfB[3 * NM + j]);
                    float e = P - ((j == r1) ? -1.f : 1.f);
                    v = e * e;
                    ((float*)DsB4)[j] = e * P * (1.f / 480.f);
                } else if (Q == 2) {
                    float d = fmaxf(taus[r0] - taus[16 + j] + 0.1f, 0.f);
                    v = (-0.5f * GnaF[j]) * d * d;
                } else {
                    float d = fmaxf(taus[r1] - taus[16 + j] + 0.1f, 0.f);
                    v = (-0.5f * GnbF[j]) * d * d;
                }
            }
            QRED4(v, 0);
            if (tx == 0) {
                g_lodd[r0] = resQ[0]; g_lodd[r1] = resQ[1];
                g_lord[r0] = resQ[2]; g_lord[r1] = resQ[3];
            }

            // backward: thread (Q, k=U) -> partial sum over j-quarter Q
            if (U < NM) {
                const int k = U;
                F2 gp; gp.f.x = GnaF[k]; gp.f.y = GnaF[k];
                const u64 gna2 = gp.u;
                gp.f.x = GnbF[k]; gp.f.y = GnbF[k];
                const u64 gnb2 = gp.u;
                float accA = 0.f, accB = 0.f;
                #pragma unroll 5
                for (int c = 0; c < 15; ++c) {
                    int jb = 15 * Q + c;
                    ulonglong2 a  = Ab8[jb * NM + k];
                    ulonglong2 dA = DsA8[jb];
                    ulonglong2 dB = DsB8[jb];
                    u64 t01 = fma2_(a.x, gna2, ONES2);
                    u64 t23 = fma2_(a.y, gna2, ONES2);
                    u64 n01 = mul2_(dA.x, a.x);
                    u64 n23 = mul2_(dA.y, a.y);
                    QUADACC(t01, t23, n01, n23, accA);
                    t01 = fma2_(a.x, gnb2, ONES2);
                    t23 = fma2_(a.y, gnb2, ONES2);
                    n01 = mul2_(dB.x, a.x);
                    n23 = mul2_(dB.y, a.y);
                    QUADACC(t01, t23, n01, n23, accB);
                }
                pfA[Q * NM + k] = accA;
                pfB[Q * NM + k] = accB;
            }
            __syncthreads();

            if (Q < 2 && U < NM) {
                const int k = U;
                const float* pf = Q ? pfB : pfA;
                float S = (pf[k] + pf[NM + k]) + (pf[2 * NM + k] + pf[3 * NM + k]);
                float s = -0.5f * (Q ? GnbF : GnaF)[k];
                float d = fmaxf(taus[Q ? r1 : r0] - taus[16 + k] + 0.1f, 0.f);
                float grad = (-2.f * S + d * d * (1.f / 61440.f)) * (s * (1.f - s));
                mg = 0.9f * mg + 0.1f * grad;
                vg = 0.999f * vg + 0.001f * grad * grad;
                gl -= 0.1f * (mg * bc1) / (sqrtf(vg * bc2) + 1e-8f);
            }
        }
        GRIDBAR();  // per-iter bar 1

        // ---------- phase B: tau grads + Adam(tau) + stop ----------
        if (!stop) {
            float v = 0.f;
            if (U < NM) {
                if (Q == 0) {
                    v = (-0.5f * GnaF[U]) * fmaxf(taus[r0] - taus[16 + U] + 0.1f, 0.f);
                } else if (Q == 1) {
                    v = (-0.5f * GnbF[U]) * fmaxf(taus[r1] - taus[16 + U] + 0.1f, 0.f);
                } else if (Q == 2) {
                    if (r0 >= 16)
                        v = ldcg(&g_Gmat[U * NM + r0 - 16]) * fmaxf(taus[U] - taus[r0] + 0.1f, 0.f);
                } else {
                    v = ldcg(&g_Gmat[U * NM + r1 - 16]) * fmaxf(taus[U] - taus[r1] + 0.1f, 0.f);
                }
            }
            QRED4(v, 0);   // resQ: 0=S1a 1=S1b 2=S2a 3=S2b

            if (b < 16) {  // block-uniform: round 2 for S2c (+ lsum on b==0)
                float w = 0.f;
                if (U < NM) {
                    if (Q == 0)
                        w = ldcg(&g_Gmat[U * NM + 224 + b]) * fmaxf(taus[U] - taus[240 + b] + 0.1f, 0.f);
                    else if (Q == 1 && b == 0)
                        w = ldcg(&g_lodd[U]) * (1.f / 960.f) + ldcg(&g_lord[U]) * (1.f / 61440.f);
                }
                QRED4(w, 4);  // resQ[4]=S2c, resQ[5]=lsum
            }

            if (tx == 0) {
                float g1 = (2.f / 61440.f) * (resQ[0] - resQ[2]);
                mt1 = 0.9f * mt1 + 0.1f * g1; vt1 = 0.999f * vt1 + 0.001f * g1 * g1;
                g_tau[r0] = taus[r0] - 0.1f * (mt1 * bc1) / (sqrtf(vt1 * bc2) + 1e-8f);
                float g2 = (2.f / 61440.f) * (resQ[1] - resQ[3]);
                mt2 = 0.9f * mt2 + 0.1f * g2; vt2 = 0.999f * vt2 + 0.001f * g2 * g2;
                g_tau[r1] = taus[r1] - 0.1f * (mt2 * bc1) / (sqrtf(vt2 * bc2) + 1e-8f);
                if (b < 16) {
                    float g3 = (2.f / 61440.f) * (0.f - resQ[4]);
                    mt3 = 0.9f * mt3 + 0.1f * g3; vt3 = 0.999f * vt3 + 0.001f * g3 * g3;
                    g_tau[240 + b] = taus[240 + b] - 0.1f * (mt3 * bc1) / (sqrtf(vt3 * bc2) + 1e-8f);
                    if (b == 0 && resQ[5] < 1e-3f) g_stop = 1;
                }
            }
        }
        GRIDBAR();  // per-iter bar 2
    }

    // ---------- epilogue: final loss at p_final ----------
    if (tx < NN) taus[tx] = ldcg(&g_tau[tx]);
    if (Q < 2 && U < NM) (Q ? GnbF : GnaF)[U] = -2.f * sigm(gl);
    __syncthreads();
    if (U < NM) {
        const int j = U;
        u64 pa0 = ONES2, pa1 = ONES2, pb0 = ONES2, pb1 = ONES2;
        #pragma unroll 5
        for (int c = 0; c < 15; ++c) {
            int kb = 15 * Q + c;
            ulonglong2 a  = At8[kb * NM + j];
            ulonglong2 ga = GnaP2[kb];
            ulonglong2 gb = GnbP2[kb];
            pa0 = mul2_(pa0, fma2_(a.x, ga.x, ONES2));
            pa1 = mul2_(pa1, fma2_(a.y, ga.y, ONES2));
            pb0 = mul2_(pb0, fma2_(a.x, gb.x, ONES2));
            pb1 = mul2_(pb1, fma2_(a.y, gb.y, ONES2));
        }
        F2 x0; x0.u = pa0; F2 x1; x1.u = pa1;
        pfA[Q * NM + j] = (x0.f.x * x0.f.y) * (x1.f.x * x1.f.y);
        x0.u = pb0; x1.u = pb1;
        pfB[Q * NM + j] = (x0.f.x * x0.f.y) * (x1.f.x * x1.f.y);
    }
    __syncthreads();
    {
        float v = 0.f;
        if (U < NM) {
            const int j = U;
            if (Q == 0) {
                float P = (pfA[j] * pfA[NM + j]) * (pfA[2 * NM + j] * pfA[3 * NM + j]);
                float e = P - ((j == r0) ? -1.f : 1.f);
                v = e * e;
            } else if (Q == 1) {
                float P = (pfB[j] * pfB[NM + j]) * (pfB[2 * NM + j] * pfB[3 * NM + j]);
                float e = P - ((j == r1) ? -1.f : 1.f);
                v = e * e;
            } else if (Q == 2) {
                float d = fmaxf(taus[r0] - taus[16 + j] + 0.1f, 0.f);
                v = (-0.5f * GnaF[j]) * d * d;
            } else {
                float d = fmaxf(taus[r1] - taus[16 + j] + 0.1f, 0.f);
                v = (-0.5f * GnbF[j]) * d * d;
            }
        }
        QRED4(v, 0);
        if (tx == 0) {
            g_lodd[r0] = resQ[0]; g_lodd[r1] = resQ[1];
            g_lord[r0] = resQ[2]; g_lord[r1] = resQ[3];
        }
    }
    GRIDBAR();  // #62
    if (b == 0) {
        float v = 0.f;
        if (U < NM) {
            if (Q == 0)      v = ldcg(&g_lodd[U]) * (1.f / 960.f);
            else if (Q == 1) v = ldcg(&g_lord[U]) * (1.f / 61440.f);
        }
        QRED4(v, 0);
        if (tx == 0) out[0] = resQ[0] + resQ[1];
    }
}

// ---------------- launch ----------------
extern "C" void kernel_launch(void* const* d_in, const int* in_sizes, int n_in,
                              void* d_out, int out_size) {
    const float* A    = (const float*)d_in[0];
    const float* Gl0  = (const float*)d_in[1];
    const float* tau0 = (const float*)d_in[2];
    gflow<<<NB, 1024>>>(A, Gl0, tau0, (float*)d_out);
}

// round 6
// speedup vs baseline: 1.8996x; 1.0735x over previous
#include <cuda_runtime.h>
#include <math.h>

#define NN 256
#define NM 240
#define NB 120
#define ITERS 30
#define PER_LAUNCH (62 * NB)   // 62 grid barriers per launch, 120 arrivals each

typedef unsigned long long u64;
union F2 { u64 u; float2 f; };
#define ONES2 0x3f8000003f800000ULL

// ---------------- device scratch ----------------
__device__ float4   g_At4[60 * NM];   // [kb*240+j] = A[j][16+4kb..16+4kb+3]
__device__ float4   g_Ab4[60 * NM];   // [jb*240+k] = A[4jb+r][16+k]
__device__ float    g_Gmat[NM * NM];  // sigmoid(Gl) snapshot (pre-update)
__device__ float    g_tau[NN];
__device__ float    g_lodd[NM];
__device__ float    g_lord[NM];
__device__ int      g_stop;
__device__ unsigned g_barcnt;         // monotonic across graph replays

// ---------------- helpers ----------------
static __device__ __forceinline__ unsigned ld_acq(const unsigned* p) {
    unsigned v; asm volatile("ld.acquire.gpu.global.u32 %0,[%1];" : "=r"(v) : "l"(p)); return v;
}
static __device__ __forceinline__ float ldcg(const float* p) {
    float v; asm volatile("ld.global.cg.f32 %0,[%1];" : "=f"(v) : "l"(p)); return v;
}
static __device__ __forceinline__ int ldcg_i(const int* p) {
    int v; asm volatile("ld.global.cg.s32 %0,[%1];" : "=r"(v) : "l"(p)); return v;
}
static __device__ __forceinline__ float rcpa(float x) {
    float r; asm("rcp.approx.f32 %0,%1;" : "=f"(r) : "f"(x)); return r;
}
static __device__ __forceinline__ u64 fma2_(u64 a, u64 b, u64 c) {
    u64 d; asm("fma.rn.f32x2 %0,%1,%2,%3;" : "=l"(d) : "l"(a), "l"(b), "l"(c)); return d;
}
static __device__ __forceinline__ u64 mul2_(u64 a, u64 b) {
    u64 d; asm("mul.rn.f32x2 %0,%1,%2;" : "=l"(d) : "l"(a), "l"(b)); return d;
}
static __device__ __forceinline__ float sigm(float x) { return 1.0f / (1.0f + __expf(-x)); }

// warp-reduce then leader writes dst[warp]; caller syncs once afterwards.
#define WRED(val, dst) do { float _v = (val);                             \
    _v += __shfl_down_sync(0xffffffffu, _v, 16);                          \
    _v += __shfl_down_sync(0xffffffffu, _v, 8);                           \
    _v += __shfl_down_sync(0xffffffffu, _v, 4);                           \
    _v += __shfl_down_sync(0xffffffffu, _v, 2);                           \
    _v += __shfl_down_sync(0xffffffffu, _v, 1);                           \
    if ((tx & 31) == 0) (dst)[tx >> 5] = _v; } while (0)

static __device__ __forceinline__ float sum8(const float* w, int g) {
    float s = 0.f;
    #pragma unroll
    for (int i = 0; i < 8; ++i) s += w[g * 8 + i];
    return s;
}

#define GRIDBAR() do { __syncthreads();                                   \
    if (tx == 0) { __threadfence(); atomicAdd(&g_barcnt, 1u);             \
        while (ld_acq(&g_barcnt) < bartgt) { } }                          \
    bartgt += NB; __syncthreads(); } while (0)

// branchless quad leave-one-out: acc += sum_i n_i/t_i ; bad set on exact-zero
#define QUADACC(t01u, t23u, n01u, n23u, acc, bad) do {                    \
    F2 _t0; _t0.u = (t01u); F2 _t1; _t1.u = (t23u);                       \
    F2 _n0; _n0.u = (n01u); F2 _n1; _n1.u = (n23u);                       \
    float _P01 = _t0.f.x * _t0.f.y;                                       \
    float _P23 = _t1.f.x * _t1.f.y;                                       \
    float _T = _P01 * _P23;                                               \
    float _r = rcpa(_T);                                                  \
    float _m1 = fmaf(_n0.f.y, _t0.f.x, _n0.f.x * _t0.f.y);                \
    float _m3 = fmaf(_n1.f.y, _t1.f.x, _n1.f.x * _t1.f.y);                \
    float _s = fmaf(_m3, _P01, _m1 * _P23);                               \
    bool _ok = (_T != 0.f);                                               \
    acc += _ok ? _s * _r : 0.f;                                           \
    bad |= !_ok; } while (0)

// ---------------- persistent kernel ----------------
__global__ void __launch_bounds__(1024, 1) gflow(
    const float* __restrict__ A, const float* __restrict__ Gl0,
    const float* __restrict__ tau0, float* __restrict__ out)
{
    const int b  = blockIdx.x;
    const int tx = threadIdx.x;
    const int Q  = tx >> 8;      // quarter 0..3
    const int U  = tx & 255;     // lane within quarter
    const int r0 = b, r1 = b + NB;

    __shared__ u64   GnaP[120], GnbP[120];      // -2*sigmoid rows r0/r1 (packed)
    __shared__ float4 DsA4[60], DsB4[60];       // (P-T)*P/480
    __shared__ float pfA[4 * NM], pfB[4 * NM];  // quarter partials
    __shared__ float taus[NN];
    __shared__ float wsum[32], wsum2[32];
    float* GnaF = (float*)GnaP;
    float* GnbF = (float*)GnbP;
    const ulonglong2* At8  = (const ulonglong2*)g_At4;
    const ulonglong2* Ab8  = (const ulonglong2*)g_Ab4;
    const ulonglong2* DsA8 = (const ulonglong2*)DsA4;
    const ulonglong2* DsB8 = (const ulonglong2*)DsB4;
    const ulonglong2* GnaP2 = (const ulonglong2*)GnaP;
    const ulonglong2* GnbP2 = (const ulonglong2*)GnbP;

    unsigned bartgt = (ld_acq(&g_barcnt) / PER_LAUNCH) * PER_LAUNCH + NB;

    // ---- init: repack A, load params into registers ----
    if (tx < 120) {
        int e = b * 120 + tx, kb = e / NM, j = e % NM;
        g_At4[e] = *(const float4*)(A + j * NN + 16 + 4 * kb);
        float4 v;
        v.x = A[(4 * kb + 0) * NN + 16 + j];
        v.y = A[(4 * kb + 1) * NN + 16 + j];
        v.z = A[(4 * kb + 2) * NN + 16 + j];
        v.w = A[(4 * kb + 3) * NN + 16 + j];
        g_Ab4[e] = v;
    }
    float gl = 0.f, mg = 0.f, vg = 0.f;     // Adam state (row = Q?r1:r0, k = U)
    if (Q < 2 && U < NM) gl = Gl0[(Q ? r1 : r0) * NM + U];
    if (tx == 0) {
        g_tau[r0] = tau0[r0]; g_tau[r1] = tau0[r1];
        if (b < 16) g_tau[240 + b] = tau0[240 + b];
        if (b == 0) g_stop = 0;
    }
    float mt1 = 0, vt1 = 0, mt2 = 0, vt2 = 0, mt3 = 0, vt3 = 0;  // tau Adam (tx 0)
    GRIDBAR();  // #1

    double b1t = 1.0, b2t = 1.0;
    int stop = 0;

    for (int t = 0; t < ITERS; ++t) {
        b1t *= 0.9; b2t *= 0.999;
        const float bc1 = (float)(1.0 / (1.0 - b1t));
        const float bc2 = (float)(1.0 / (1.0 - b2t));
        if (!stop) stop = ldcg_i(&g_stop);

        // ---------- phase A ----------
        if (!stop) {
            if (tx < NN) taus[tx] = ldcg(&g_tau[tx]);
            if (Q < 2 && U < NM) {
                float s = sigm(gl);
                (Q ? GnbF : GnaF)[U] = -2.f * s;
                g_Gmat[(Q ? r1 : r0) * NM + U] = s;
            }
            __syncthreads();

            // forward: thread (Q, j=U) -> product over k-quarter Q (prefetched)
            if (U < NM) {
                const int j = U;
                const ulonglong2* ap = At8 + (15 * Q) * NM + j;
                ulonglong2 an = ap[0];
                u64 pa0 = ONES2, pa1 = ONES2, pb0 = ONES2, pb1 = ONES2;
                #pragma unroll 5
                for (int c = 0; c < 15; ++c) {
                    ulonglong2 a = an;
                    if (c < 14) an = ap[(c + 1) * NM];
                    ulonglong2 ga = GnaP2[15 * Q + c];
                    ulonglong2 gb = GnbP2[15 * Q + c];
                    pa0 = mul2_(pa0, fma2_(a.x, ga.x, ONES2));
                    pa1 = mul2_(pa1, fma2_(a.y, ga.y, ONES2));
                    pb0 = mul2_(pb0, fma2_(a.x, gb.x, ONES2));
                    pb1 = mul2_(pb1, fma2_(a.y, gb.y, ONES2));
                }
                F2 x0; x0.u = pa0; F2 x1; x1.u = pa1;
                pfA[Q * NM + j] = (x0.f.x * x0.f.y) * (x1.f.x * x1.f.y);
                x0.u = pb0; x1.u = pb1;
                pfB[Q * NM + j] = (x0.f.x * x0.f.y) * (x1.f.x * x1.f.y);
            }
            __syncthreads();

            // per-quarter epilogue: Q0 la+DsA, Q1 lb+DsB, Q2 lo0, Q3 lo1
            float v = 0.f;
            if (U < NM) {
                const int j = U;
                if (Q == 0) {
                    float P = (pfA[j] * pfA[NM + j]) * (pfA[2 * NM + j] * pfA[3 * NM + j]);
                    float e = P - ((j == r0) ? -1.f : 1.f);
                    v = e * e;
                    ((float*)DsA4)[j] = e * P * (1.f / 480.f);
                } else if (Q == 1) {
                    float P = (pfB[j] * pfB[NM + j]) * (pfB[2 * NM + j] * pfB[3 * NM + j]);
                    float e = P - ((j == r1) ? -1.f : 1.f);
                    v = e * e;
                    ((float*)DsB4)[j] = e * P * (1.f / 480.f);
                } else if (Q == 2) {
                    float d = fmaxf(taus[r0] - taus[16 + j] + 0.1f, 0.f);
                    v = (-0.5f * GnaF[j]) * d * d;
                } else {
                    float d = fmaxf(taus[r1] - taus[16 + j] + 0.1f, 0.f);
                    v = (-0.5f * GnbF[j]) * d * d;
                }
            }
            WRED(v, wsum);
            __syncthreads();   // publishes Ds + wsum
            if (tx == 0) {
                g_lodd[r0] = sum8(wsum, 0); g_lodd[r1] = sum8(wsum, 1);
                g_lord[r0] = sum8(wsum, 2); g_lord[r1] = sum8(wsum, 3);
            }

            // backward: thread (Q, k=U) -> partial sum over j-quarter Q
            if (U < NM) {
                const int k = U;
                F2 gp; gp.f.x = GnaF[k]; gp.f.y = GnaF[k];
                const u64 gna2 = gp.u;
                gp.f.x = GnbF[k]; gp.f.y = GnbF[k];
                const u64 gnb2 = gp.u;
                float accA = 0.f, accB = 0.f;
                bool bad = false;
                const ulonglong2* abp = Ab8 + (15 * Q) * NM + k;
                ulonglong2 an = abp[0];
                #pragma unroll 5
                for (int c = 0; c < 15; ++c) {
                    ulonglong2 a = an;
                    if (c < 14) an = abp[(c + 1) * NM];
                    ulonglong2 dA = DsA8[15 * Q + c];
                    ulonglong2 dB = DsB8[15 * Q + c];
                    u64 t01 = fma2_(a.x, gna2, ONES2);
                    u64 t23 = fma2_(a.y, gna2, ONES2);
                    u64 n01 = mul2_(dA.x, a.x);
                    u64 n23 = mul2_(dA.y, a.y);
                    QUADACC(t01, t23, n01, n23, accA, bad);
                    t01 = fma2_(a.x, gnb2, ONES2);
                    t23 = fma2_(a.y, gnb2, ONES2);
                    n01 = mul2_(dB.x, a.x);
                    n23 = mul2_(dB.y, a.y);
                    QUADACC(t01, t23, n01, n23, accB, bad);
                }
                if (bad) {   // exact-zero term in some quad: redo safely (rare)
                    accA = 0.f; accB = 0.f;
                    const float gna = GnaF[k], gnb = GnbF[k];
                    for (int c = 0; c < 15; ++c) {
                        int jb = 15 * Q + c;
                        float4 a4 = g_Ab4[jb * NM + k];
                        float4 dA = DsA4[jb], dB = DsB4[jb];
                        const float* av = (const float*)&a4;
                        const float* dv = (const float*)&dA;
                        const float* ev = (const float*)&dB;
                        #pragma unroll
                        for (int e2 = 0; e2 < 4; ++e2) {
                            float tA = fmaf(av[e2], gna, 1.f);
                            float tB = fmaf(av[e2], gnb, 1.f);
                            accA += (tA != 0.f) ? __fdividef(dv[e2] * av[e2], tA) : 0.f;
                            accB += (tB != 0.f) ? __fdividef(ev[e2] * av[e2], tB) : 0.f;
                        }
                    }
                }
                pfA[Q * NM + k] = accA;
                pfB[Q * NM + k] = accB;
            }
            __syncthreads();

            if (Q < 2 && U < NM) {
                const int k = U;
                const float* pf = Q ? pfB : pfA;
                float S = (pf[k] + pf[NM + k]) + (pf[2 * NM + k] + pf[3 * NM + k]);
                float s = -0.5f * (Q ? GnbF : GnaF)[k];
                float d = fmaxf(taus[Q ? r1 : r0] - taus[16 + k] + 0.1f, 0.f);
                float grad = (-2.f * S + d * d * (1.f / 61440.f)) * (s * (1.f - s));
                mg = 0.9f * mg + 0.1f * grad;
                vg = 0.999f * vg + 0.001f * grad * grad;
                gl -= 0.1f * (mg * bc1) / (sqrtf(vg * bc2) + 1e-8f);
            }
        }
        GRIDBAR();  // per-iter bar 1

        // ---------- phase B: tau grads + Adam(tau) + stop (one sync) ----------
        if (!stop) {
            float v = 0.f, w = 0.f;
            if (U < NM) {
                if (Q == 0) {
                    v = (-0.5f * GnaF[U]) * fmaxf(taus[r0] - taus[16 + U] + 0.1f, 0.f);
                } else if (Q == 1) {
                    v = (-0.5f * GnbF[U]) * fmaxf(taus[r1] - taus[16 + U] + 0.1f, 0.f);
                } else if (Q == 2) {
                    if (r0 >= 16)
                        v = ldcg(&g_Gmat[U * NM + r0 - 16]) * fmaxf(taus[U] - taus[r0] + 0.1f, 0.f);
                } else {
                    v = ldcg(&g_Gmat[U * NM + r1 - 16]) * fmaxf(taus[U] - taus[r1] + 0.1f, 0.f);
                }
                if (b < 16) {
                    if (Q == 0)
                        w = ldcg(&g_Gmat[U * NM + 224 + b]) * fmaxf(taus[U] - taus[240 + b] + 0.1f, 0.f);
                    else if (Q == 1 && b == 0)
                        w = ldcg(&g_lodd[U]) * (1.f / 960.f) + ldcg(&g_lord[U]) * (1.f / 61440.f);
                }
            }
            WRED(v, wsum);
            WRED(w, wsum2);
            __syncthreads();

            if (tx == 0) {
                float g1 = (2.f / 61440.f) * (sum8(wsum, 0) - sum8(wsum, 2));
                mt1 = 0.9f * mt1 + 0.1f * g1; vt1 = 0.999f * vt1 + 0.001f * g1 * g1;
                g_tau[r0] = taus[r0] - 0.1f * (mt1 * bc1) / (sqrtf(vt1 * bc2) + 1e-8f);
                float g2 = (2.f / 61440.f) * (sum8(wsum, 1) - sum8(wsum, 3));
                mt2 = 0.9f * mt2 + 0.1f * g2; vt2 = 0.999f * vt2 + 0.001f * g2 * g2;
                g_tau[r1] = taus[r1] - 0.1f * (mt2 * bc1) / (sqrtf(vt2 * bc2) + 1e-8f);
                if (b < 16) {
                    float g3 = (2.f / 61440.f) * (0.f - sum8(wsum2, 0));
                    mt3 = 0.9f * mt3 + 0.1f * g3; vt3 = 0.999f * vt3 + 0.001f * g3 * g3;
                    g_tau[240 + b] = taus[240 + b] - 0.1f * (mt3 * bc1) / (sqrtf(vt3 * bc2) + 1e-8f);
                    if (b == 0 && sum8(wsum2, 1) < 1e-3f) g_stop = 1;
                }
            }
        }
        GRIDBAR();  // per-iter bar 2
    }

    // ---------- epilogue: final loss at p_final ----------
    if (tx < NN) taus[tx] = ldcg(&g_tau[tx]);
    if (Q < 2 && U < NM) (Q ? GnbF : GnaF)[U] = -2.f * sigm(gl);
    __syncthreads();
    if (U < NM) {
        const int j = U;
        const ulonglong2* ap = At8 + (15 * Q) * NM + j;
        ulonglong2 an = ap[0];
        u64 pa0 = ONES2, pa1 = ONES2, pb0 = ONES2, pb1 = ONES2;
        #pragma unroll 5
        for (int c = 0; c < 15; ++c) {
            ulonglong2 a = an;
            if (c < 14) an = ap[(c + 1) * NM];
            ulonglong2 ga = GnaP2[15 * Q + c];
            ulonglong2 gb = GnbP2[15 * Q + c];
            pa0 = mul2_(pa0, fma2_(a.x, ga.x, ONES2));
            pa1 = mul2_(pa1, fma2_(a.y, ga.y, ONES2));
            pb0 = mul2_(pb0, fma2_(a.x, gb.x, ONES2));
            pb1 = mul2_(pb1, fma2_(a.y, gb.y, ONES2));
        }
        F2 x0; x0.u = pa0; F2 x1; x1.u = pa1;
        pfA[Q * NM + j] = (x0.f.x * x0.f.y) * (x1.f.x * x1.f.y);
        x0.u = pb0; x1.u = pb1;
        pfB[Q * NM + j] = (x0.f.x * x0.f.y) * (x1.f.x * x1.f.y);
    }
    __syncthreads();
    {
        float v = 0.f;
        if (U < NM) {
            const int j = U;
            if (Q == 0) {
                float P = (pfA[j] * pfA[NM + j]) * (pfA[2 * NM + j] * pfA[3 * NM + j]);
                float e = P - ((j == r0) ? -1.f : 1.f);
                v = e * e;
            } else if (Q == 1) {
                float P = (pfB[j] * pfB[NM + j]) * (pfB[2 * NM + j] * pfB[3 * NM + j]);
                float e = P - ((j == r1) ? -1.f : 1.f);
                v = e * e;
            } else if (Q == 2) {
                float d = fmaxf(taus[r0] - taus[16 + j] + 0.1f, 0.f);
                v = (-0.5f * GnaF[j]) * d * d;
            } else {
                float d = fmaxf(taus[r1] - taus[16 + j] + 0.1f, 0.f);
                v = (-0.5f * GnbF[j]) * d * d;
            }
        }
        WRED(v, wsum);
        __syncthreads();
        if (tx == 0) {
            g_lodd[r0] = sum8(wsum, 0); g_lodd[r1] = sum8(wsum, 1);
            g_lord[r0] = sum8(wsum, 2); g_lord[r1] = sum8(wsum, 3);
        }
    }
    GRIDBAR();  // #62
    if (b == 0) {
        float v = 0.f;
        if (U < NM) {
            if (Q == 0)      v = ldcg(&g_lodd[U]) * (1.f / 960.f);
            else if (Q == 1) v = ldcg(&g_lord[U]) * (1.f / 61440.f);
        }
        WRED(v, wsum);
        __syncthreads();
        if (tx == 0) out[0] = sum8(wsum, 0) + sum8(wsum, 1);
    }
}

// ---------------- launch ----------------
extern "C" void kernel_launch(void* const* d_in, const int* in_sizes, int n_in,
                              void* d_out, int out_size) {
    const float* A    = (const float*)d_in[0];
    const float* Gl0  = (const float*)d_in[1];
    const float* tau0 = (const float*)d_in[2];
    gflow<<<NB, 1024>>>(A, Gl0, tau0, (float*)d_out);
}